// round 7
// baseline (speedup 1.0000x reference)
#include <cuda_runtime.h>
#include <math.h>

// Problem constants
#define MTOT 32768      // B*T = 8*4096
#define DIN  512        // D
#define DC   256        // Dc
#define NQ   8
#define BINS 1024
#define RVQ_ROWS 64
#define RVQ_BLOCKS (MTOT / RVQ_ROWS)   // 512

#define OUT_ELEMS   ((size_t)MTOT * DIN)        // 16777216
#define IDX_ELEMS   ((size_t)NQ * MTOT)         // 262144

// Scratch (static device globals; allocation-free), 256B aligned for float4.
__device__ __align__(256) float  g_h[MTOT * DC];       // 32 MB
__device__ __align__(256) float  g_res[MTOT * DC];     // 32 MB
__device__ __align__(256) float  g_q[MTOT * DC];       // 32 MB (sum of gathered codewords)
__device__ __align__(256) float  g_e2[NQ * BINS];
__device__ __align__(256) double g_partial[NQ * RVQ_BLOCKS];
__device__ __align__(256) float  g_idx_sink[IDX_ELEMS];
__device__ __align__(256) float  g_commit_sink[16];

// ---------------------------------------------------------------------------
// XLA/Eigen rational tanh for f32 (what jnp.tanh lowers to on GPU).
// ---------------------------------------------------------------------------
__device__ __forceinline__ float xla_tanh(float x) {
    float ax = fabsf(x);
    float xc = fminf(fmaxf(x, -9.0f), 9.0f);
    float x2 = __fmul_rn(xc, xc);
    float p = -2.76076847742355e-16f;
    p = __fadd_rn(__fmul_rn(p, x2),  2.00018790482477e-13f);
    p = __fadd_rn(__fmul_rn(p, x2), -8.60467152213735e-11f);
    p = __fadd_rn(__fmul_rn(p, x2),  5.12229709037114e-08f);
    p = __fadd_rn(__fmul_rn(p, x2),  1.48572235717979e-05f);
    p = __fadd_rn(__fmul_rn(p, x2),  6.37261928875436e-04f);
    p = __fadd_rn(__fmul_rn(p, x2),  4.89352455891786e-03f);
    float num = __fmul_rn(xc, p);
    float q = 1.19825839466702e-06f;
    q = __fadd_rn(__fmul_rn(q, x2), 1.18534705686654e-04f);
    q = __fadd_rn(__fmul_rn(q, x2), 2.26843463243900e-03f);
    q = __fadd_rn(__fmul_rn(q, x2), 4.89352518554385e-03f);
    float r = __fdiv_rn(num, q);
    return (ax < 0.0004f) ? x : r;
}

// ---------------------------------------------------------------------------
// XLA-style warp row reduction (fp32, no fma, ascending strided + shfl tree).
// ---------------------------------------------------------------------------
__device__ __forceinline__ float warp_rowsum_sq(const float* __restrict__ p, int lane) {
    float s = 0.f;
    #pragma unroll
    for (int t = 0; t < DC / 32; t++) {
        float v = p[lane + 32 * t];
        s = __fadd_rn(s, __fmul_rn(v, v));
    }
    #pragma unroll
    for (int o = 16; o; o >>= 1)
        s = __fadd_rn(s, __shfl_down_sync(0xffffffffu, s, o));
    return s;
}

__global__ void e2_kernel(const float* __restrict__ cb) {
    int warp = (blockIdx.x * blockDim.x + threadIdx.x) >> 5;
    int lane = threadIdx.x & 31;
    int nwarps = (gridDim.x * blockDim.x) >> 5;
    for (int row = warp; row < NQ * BINS; row += nwarps) {
        float s = warp_rowsum_sq(cb + (size_t)row * DC, lane);
        if (lane == 0) g_e2[row] = s;
    }
}

// ---------------------------------------------------------------------------
// proj_in: h = xla_tanh(x @ in_w^T + in_b). 128x128x16, 8x8 scalar microtile.
// Serial k-ascending fp32 FMA chain per output (bit-stable).
// ---------------------------------------------------------------------------
__global__ __launch_bounds__(256, 2)
void proj_in_kernel(const float* __restrict__ A,
                    const float* __restrict__ Bw,
                    const float* __restrict__ bias) {
    __shared__ float As[16][128];
    __shared__ float Bs[16][128];

    int tid = threadIdx.x;
    int tx = tid & 15, ty = tid >> 4;
    int rowBase = blockIdx.x * 128;
    int colBase = blockIdx.y * 128;

    float acc[8][8];
    #pragma unroll
    for (int i = 0; i < 8; i++)
        #pragma unroll
        for (int j = 0; j < 8; j++) acc[i][j] = 0.f;

    for (int kc = 0; kc < DIN; kc += 16) {
        #pragma unroll
        for (int l = 0; l < 2; l++) {
            int id = tid + l * 256;
            int r = id >> 2, kq = (id & 3) * 4;
            float4 v = *(const float4*)(A + (size_t)(rowBase + r) * DIN + kc + kq);
            As[kq + 0][r] = v.x; As[kq + 1][r] = v.y;
            As[kq + 2][r] = v.z; As[kq + 3][r] = v.w;
            float4 b = *(const float4*)(Bw + (size_t)(colBase + r) * DIN + kc + kq);
            Bs[kq + 0][r] = b.x; Bs[kq + 1][r] = b.y;
            Bs[kq + 2][r] = b.z; Bs[kq + 3][r] = b.w;
        }
        __syncthreads();
        #pragma unroll
        for (int kk = 0; kk < 16; kk++) {
            float a[8], b[8];
            #pragma unroll
            for (int i = 0; i < 8; i++) a[i] = As[kk][ty * 8 + i];
            #pragma unroll
            for (int j = 0; j < 8; j++) b[j] = Bs[kk][tx * 8 + j];
            #pragma unroll
            for (int i = 0; i < 8; i++)
                #pragma unroll
                for (int j = 0; j < 8; j++) acc[i][j] = fmaf(a[i], b[j], acc[i][j]);
        }
        __syncthreads();
    }

    #pragma unroll
    for (int i = 0; i < 8; i++) {
        int row = rowBase + ty * 8 + i;
        #pragma unroll
        for (int j = 0; j < 8; j++) {
            int col = colBase + tx * 8 + j;
            float pre = __fadd_rn(acc[i][j], bias[col]);
            float t = xla_tanh(pre);
            size_t off = (size_t)row * DC + col;
            g_h[off] = t;
            g_res[off] = t;
        }
    }
}

// ---------------------------------------------------------------------------
// lexicographic (value, index) min
// ---------------------------------------------------------------------------
__device__ __forceinline__ void amin_merge(float& bv, int& bi, float v, int i) {
    if (v < bv || (v == bv && i < bi)) { bv = v; bi = i; }
}

// ---------------------------------------------------------------------------
// One RVQ step. 64-row tiles (512 CTAs -> ~3 CTAs/SM resident), BK=32
// (half the barriers), 4x8 scalar microtile. dist = (r2 - 2*re) + e2 fp32,
// re via serial k-ascending FMA chain; fp32 lexicographic argmin.
// ---------------------------------------------------------------------------
__global__ __launch_bounds__(256, 3)
void rvq_step_kernel(const float* __restrict__ cb_all, int step,
                     float* __restrict__ idx_out) {
    const float* cb = cb_all + (size_t)step * BINS * DC;
    const float* e2 = g_e2 + step * BINS;

    __shared__ float As[32][64];     // 8 KB
    __shared__ float Bs[32][128];    // 16 KB
    __shared__ float r2row[RVQ_ROWS];
    __shared__ float candV[RVQ_ROWS];
    __shared__ int   candI[RVQ_ROWS];
    __shared__ float bestV[RVQ_ROWS];
    __shared__ int   bestI[RVQ_ROWS];
    __shared__ double rs[256];

    int tid = threadIdx.x;
    int tx = tid & 15, ty = tid >> 4;        // tx: 8-bin group, ty: 4-row group
    int wid = tid >> 5, lane = tid & 31;
    int rowBase = blockIdx.x * RVQ_ROWS;

    // r2 per row (XLA row-reduce pattern): 8 warps x 8 rows
    for (int r = wid * 8; r < wid * 8 + 8; r++) {
        float s = warp_rowsum_sq(g_res + (size_t)(rowBase + r) * DC, lane);
        if (lane == 0) r2row[r] = s;
    }
    if (tid < RVQ_ROWS) { bestV[tid] = 3.4e38f; bestI[tid] = 0x7fffffff; }
    __syncthreads();

    for (int bc = 0; bc < BINS; bc += 128) {
        float acc[4][8];
        #pragma unroll
        for (int i = 0; i < 4; i++)
            #pragma unroll
            for (int j = 0; j < 8; j++) acc[i][j] = 0.f;

        for (int kc = 0; kc < DC; kc += 32) {
            #pragma unroll
            for (int l = 0; l < 2; l++) {   // As: 64 rows x 32 k = 512 float4
                int id = tid + l * 256;
                int r = id >> 3, kq = (id & 7) * 4;
                float4 v = *(const float4*)(g_res + (size_t)(rowBase + r) * DC + kc + kq);
                As[kq + 0][r] = v.x; As[kq + 1][r] = v.y;
                As[kq + 2][r] = v.z; As[kq + 3][r] = v.w;
            }
            #pragma unroll
            for (int l = 0; l < 4; l++) {   // Bs: 128 rows x 32 k = 1024 float4
                int id = tid + l * 256;
                int r = id >> 3, kq = (id & 7) * 4;
                float4 b = *(const float4*)(cb + (size_t)(bc + r) * DC + kc + kq);
                Bs[kq + 0][r] = b.x; Bs[kq + 1][r] = b.y;
                Bs[kq + 2][r] = b.z; Bs[kq + 3][r] = b.w;
            }
            __syncthreads();
            #pragma unroll
            for (int kk = 0; kk < 32; kk++) {
                float a[4], b[8];
                #pragma unroll
                for (int i = 0; i < 4; i++) a[i] = As[kk][ty * 4 + i];
                #pragma unroll
                for (int j = 0; j < 8; j++) b[j] = Bs[kk][tx * 8 + j];
                #pragma unroll
                for (int i = 0; i < 4; i++)
                    #pragma unroll
                    for (int j = 0; j < 8; j++) acc[i][j] = fmaf(a[i], b[j], acc[i][j]);
            }
            __syncthreads();
        }

        float ee[8];
        #pragma unroll
        for (int j = 0; j < 8; j++) ee[j] = e2[bc + tx * 8 + j];

        #pragma unroll
        for (int i = 0; i < 4; i++) {
            int row = ty * 4 + i;
            float r2 = r2row[row];
            float bv = 3.4e38f; int bi = 0x7fffffff;
            #pragma unroll
            for (int j = 0; j < 8; j++) {
                // (r2 - 2*re) + e2, non-contracted, matching XLA elementwise
                float d = __fadd_rn(__fsub_rn(r2, __fmul_rn(2.0f, acc[i][j])), ee[j]);
                amin_merge(bv, bi, d, bc + tx * 8 + j);
            }
            #pragma unroll
            for (int m = 1; m <= 8; m <<= 1) {
                float ov = __shfl_xor_sync(0xffffffffu, bv, m);
                int   oi = __shfl_xor_sync(0xffffffffu, bi, m);
                amin_merge(bv, bi, ov, oi);
            }
            if (tx == 0) { candV[row] = bv; candI[row] = bi; }
        }
        __syncthreads();
        if (tid < RVQ_ROWS) {
            float bv = bestV[tid]; int bi = bestI[tid];
            amin_merge(bv, bi, candV[tid], candI[tid]);
            bestV[tid] = bv; bestI[tid] = bi;
        }
        __syncthreads();
    }

    if (tid < RVQ_ROWS)
        idx_out[(size_t)step * MTOT + rowBase + tid] = (float)bestI[tid];

    // gather + residual update + q accumulation + commit partial
    double csum = 0.0;
    for (int r = 0; r < RVQ_ROWS; r++) {
        int gi = bestI[r];
        float c = cb[(size_t)gi * DC + tid];
        size_t off = (size_t)(rowBase + r) * DC + tid;
        float old = g_res[off];
        float t = __fsub_rn(c, old);
        csum += (double)__fmul_rn(t, t);
        g_res[off] = __fsub_rn(old, c);
        g_q[off] = (step == 0) ? c : __fadd_rn(g_q[off], c);
    }
    rs[tid] = csum;
    __syncthreads();
    #pragma unroll
    for (int s = 128; s; s >>= 1) {
        if (tid < s) rs[tid] += rs[tid + s];
        __syncthreads();
    }
    if (tid == 0) g_partial[step * RVQ_BLOCKS + blockIdx.x] = rs[0];
}

__global__ void finalize_kernel(float* __restrict__ commit_out) {
    if (blockIdx.x == 0 && threadIdx.x == 0) {
        double total = 0.0;
        for (int n = 0; n < NQ; n++) {
            double s = 0.0;
            for (int b = 0; b < RVQ_BLOCKS; b++) s += g_partial[n * RVQ_BLOCKS + b];
            total += s / ((double)MTOT * (double)DC);
        }
        *commit_out = (float)(0.1 * total);
    }
}

// ---------------------------------------------------------------------------
// proj_out: out = (h + (sumq - h)) @ out_w^T + out_b. 128x128x16, 8x8 scalar.
// ---------------------------------------------------------------------------
__global__ __launch_bounds__(256, 2)
void proj_out_kernel(const float* __restrict__ Bw,
                     const float* __restrict__ bias,
                     float* __restrict__ C) {
    __shared__ float As[16][128];
    __shared__ float Bs[16][128];

    int tid = threadIdx.x;
    int tx = tid & 15, ty = tid >> 4;
    int rowBase = blockIdx.x * 128;
    int colBase = blockIdx.y * 128;

    float acc[8][8];
    #pragma unroll
    for (int i = 0; i < 8; i++)
        #pragma unroll
        for (int j = 0; j < 8; j++) acc[i][j] = 0.f;

    for (int kc = 0; kc < DC; kc += 16) {
        #pragma unroll
        for (int l = 0; l < 2; l++) {
            int id = tid + l * 256;
            int r = id >> 2, kq = (id & 3) * 4;
            size_t off = (size_t)(rowBase + r) * DC + kc + kq;
            float4 h4 = *(const float4*)(g_h + off);
            float4 q4 = *(const float4*)(g_q + off);
            // quantized = h + (sumq - h), elementwise, non-contracted
            As[kq + 0][r] = __fadd_rn(h4.x, __fsub_rn(q4.x, h4.x));
            As[kq + 1][r] = __fadd_rn(h4.y, __fsub_rn(q4.y, h4.y));
            As[kq + 2][r] = __fadd_rn(h4.z, __fsub_rn(q4.z, h4.z));
            As[kq + 3][r] = __fadd_rn(h4.w, __fsub_rn(q4.w, h4.w));
            float4 b = *(const float4*)(Bw + (size_t)(colBase + r) * DC + kc + kq);
            Bs[kq + 0][r] = b.x; Bs[kq + 1][r] = b.y;
            Bs[kq + 2][r] = b.z; Bs[kq + 3][r] = b.w;
        }
        __syncthreads();
        #pragma unroll
        for (int kk = 0; kk < 16; kk++) {
            float a[8], b[8];
            #pragma unroll
            for (int i = 0; i < 8; i++) a[i] = As[kk][ty * 8 + i];
            #pragma unroll
            for (int j = 0; j < 8; j++) b[j] = Bs[kk][tx * 8 + j];
            #pragma unroll
            for (int i = 0; i < 8; i++)
                #pragma unroll
                for (int j = 0; j < 8; j++) acc[i][j] = fmaf(a[i], b[j], acc[i][j]);
        }
        __syncthreads();
    }

    #pragma unroll
    for (int i = 0; i < 8; i++) {
        int row = rowBase + ty * 8 + i;
        #pragma unroll
        for (int j = 0; j < 8; j++) {
            int col = colBase + tx * 8 + j;
            C[(size_t)row * DIN + col] = __fadd_rn(acc[i][j], bias[col]);
        }
    }
}

// ---------------------------------------------------------------------------
extern "C" void kernel_launch(void* const* d_in, const int* in_sizes, int n_in,
                              void* d_out, int out_size) {
    const float* x     = (const float*)d_in[0];   // [8,4096,512]
    const float* in_w  = (const float*)d_in[1];   // [256,512]
    const float* in_b  = (const float*)d_in[2];   // [256]
    const float* out_w = (const float*)d_in[3];   // [512,256]
    const float* out_b = (const float*)d_in[4];   // [512]
    const float* cb    = (const float*)d_in[5];   // [8,1024,256]

    float* out_f = (float*)d_out;

    float* idx_f    = nullptr;
    float* commit_f = nullptr;
    if ((size_t)out_size >= OUT_ELEMS + IDX_ELEMS + 1) {
        idx_f    = out_f + OUT_ELEMS;
        commit_f = out_f + OUT_ELEMS + IDX_ELEMS;
    } else if ((size_t)out_size >= OUT_ELEMS + IDX_ELEMS) {
        idx_f = out_f + OUT_ELEMS;
    }
    if (!idx_f)    cudaGetSymbolAddress((void**)&idx_f,    g_idx_sink);
    if (!commit_f) cudaGetSymbolAddress((void**)&commit_f, g_commit_sink);

    e2_kernel<<<64, 256>>>(cb);

    {
        dim3 grid(MTOT / 128, DC / 128);
        proj_in_kernel<<<grid, 256>>>(x, in_w, in_b);
    }

    for (int n = 0; n < NQ; n++)
        rvq_step_kernel<<<RVQ_BLOCKS, 256>>>(cb, n, idx_f);

    finalize_kernel<<<1, 32>>>(commit_f);

    {
        dim3 grid(MTOT / 128, DIN / 128);
        proj_out_kernel<<<grid, 256>>>(out_w, out_b, out_f);
    }
}

// round 9
// speedup vs baseline: 2.1295x; 2.1295x over previous
#include <cuda_runtime.h>
#include <math.h>

// Problem constants
#define MTOT 32768      // B*T = 8*4096
#define DIN  512        // D
#define DC   256        // Dc
#define NQ   8
#define BINS 1024
#define RVQ_BLOCKS (MTOT / 128)   // 256

#define OUT_ELEMS   ((size_t)MTOT * DIN)        // 16777216
#define IDX_ELEMS   ((size_t)NQ * MTOT)         // 262144

// Scratch (static device globals; allocation-free), 256B aligned for float4.
__device__ __align__(256) float  g_h[MTOT * DC];       // 32 MB
__device__ __align__(256) float  g_res[MTOT * DC];     // 32 MB
__device__ __align__(256) float  g_q[MTOT * DC];       // 32 MB (sum of gathered codewords)
__device__ __align__(256) float  g_e2[NQ * BINS];
__device__ __align__(256) double g_partial[NQ * RVQ_BLOCKS];
__device__ __align__(256) float  g_idx_sink[IDX_ELEMS];
__device__ __align__(256) float  g_commit_sink[16];

// ---------------------------------------------------------------------------
// tf32 helpers (legacy warp-level tensor core MMA; supported on sm_100)
// ---------------------------------------------------------------------------
__device__ __forceinline__ unsigned f2tf(float x) {
    unsigned u; asm("cvt.rna.tf32.f32 %0, %1;" : "=r"(u) : "f"(x)); return u;
}
__device__ __forceinline__ void mma_tf32(float* c,
                                         unsigned a0, unsigned a1, unsigned a2, unsigned a3,
                                         unsigned b0, unsigned b1) {
    asm("mma.sync.aligned.m16n8k8.row.col.f32.tf32.tf32.f32 "
        "{%0,%1,%2,%3}, {%4,%5,%6,%7}, {%8,%9}, {%0,%1,%2,%3};"
        : "+f"(c[0]), "+f"(c[1]), "+f"(c[2]), "+f"(c[3])
        : "r"(a0), "r"(a1), "r"(a2), "r"(a3), "r"(b0), "r"(b1));
}

// ---------------------------------------------------------------------------
// XLA/Eigen rational tanh for f32 (what jnp.tanh lowers to on GPU).
// ---------------------------------------------------------------------------
__device__ __forceinline__ float xla_tanh(float x) {
    float ax = fabsf(x);
    float xc = fminf(fmaxf(x, -9.0f), 9.0f);
    float x2 = __fmul_rn(xc, xc);
    float p = -2.76076847742355e-16f;
    p = __fadd_rn(__fmul_rn(p, x2),  2.00018790482477e-13f);
    p = __fadd_rn(__fmul_rn(p, x2), -8.60467152213735e-11f);
    p = __fadd_rn(__fmul_rn(p, x2),  5.12229709037114e-08f);
    p = __fadd_rn(__fmul_rn(p, x2),  1.48572235717979e-05f);
    p = __fadd_rn(__fmul_rn(p, x2),  6.37261928875436e-04f);
    p = __fadd_rn(__fmul_rn(p, x2),  4.89352455891786e-03f);
    float num = __fmul_rn(xc, p);
    float q = 1.19825839466702e-06f;
    q = __fadd_rn(__fmul_rn(q, x2), 1.18534705686654e-04f);
    q = __fadd_rn(__fmul_rn(q, x2), 2.26843463243900e-03f);
    q = __fadd_rn(__fmul_rn(q, x2), 4.89352518554385e-03f);
    float r = __fdiv_rn(num, q);
    return (ax < 0.0004f) ? x : r;
}

// ---------------------------------------------------------------------------
// XLA-style warp row reduction (fp32, no fma, ascending strided + shfl tree).
// ---------------------------------------------------------------------------
__device__ __forceinline__ float warp_rowsum_sq(const float* __restrict__ p, int lane) {
    float s = 0.f;
    #pragma unroll
    for (int t = 0; t < DC / 32; t++) {
        float v = p[lane + 32 * t];
        s = __fadd_rn(s, __fmul_rn(v, v));
    }
    #pragma unroll
    for (int o = 16; o; o >>= 1)
        s = __fadd_rn(s, __shfl_down_sync(0xffffffffu, s, o));
    return s;
}

__global__ void e2_kernel(const float* __restrict__ cb) {
    int warp = (blockIdx.x * blockDim.x + threadIdx.x) >> 5;
    int lane = threadIdx.x & 31;
    int nwarps = (gridDim.x * blockDim.x) >> 5;
    for (int row = warp; row < NQ * BINS; row += nwarps) {
        float s = warp_rowsum_sq(cb + (size_t)row * DC, lane);
        if (lane == 0) g_e2[row] = s;
    }
}

// ---------------------------------------------------------------------------
// proj_in: h = xla_tanh(x @ in_w^T + in_b). 128x128x16, 8x8 scalar microtile.
// Serial k-ascending fp32 FMA chain per output (bit-stable).
// ---------------------------------------------------------------------------
__global__ __launch_bounds__(256, 2)
void proj_in_kernel(const float* __restrict__ A,
                    const float* __restrict__ Bw,
                    const float* __restrict__ bias) {
    __shared__ float As[16][128];
    __shared__ float Bs[16][128];

    int tid = threadIdx.x;
    int tx = tid & 15, ty = tid >> 4;
    int rowBase = blockIdx.x * 128;
    int colBase = blockIdx.y * 128;

    float acc[8][8];
    #pragma unroll
    for (int i = 0; i < 8; i++)
        #pragma unroll
        for (int j = 0; j < 8; j++) acc[i][j] = 0.f;

    for (int kc = 0; kc < DIN; kc += 16) {
        #pragma unroll
        for (int l = 0; l < 2; l++) {
            int id = tid + l * 256;
            int r = id >> 2, kq = (id & 3) * 4;
            float4 v = *(const float4*)(A + (size_t)(rowBase + r) * DIN + kc + kq);
            As[kq + 0][r] = v.x; As[kq + 1][r] = v.y;
            As[kq + 2][r] = v.z; As[kq + 3][r] = v.w;
            float4 b = *(const float4*)(Bw + (size_t)(colBase + r) * DIN + kc + kq);
            Bs[kq + 0][r] = b.x; Bs[kq + 1][r] = b.y;
            Bs[kq + 2][r] = b.z; Bs[kq + 3][r] = b.w;
        }
        __syncthreads();
        #pragma unroll
        for (int kk = 0; kk < 16; kk++) {
            float a[8], b[8];
            #pragma unroll
            for (int i = 0; i < 8; i++) a[i] = As[kk][ty * 8 + i];
            #pragma unroll
            for (int j = 0; j < 8; j++) b[j] = Bs[kk][tx * 8 + j];
            #pragma unroll
            for (int i = 0; i < 8; i++)
                #pragma unroll
                for (int j = 0; j < 8; j++) acc[i][j] = fmaf(a[i], b[j], acc[i][j]);
        }
        __syncthreads();
    }

    #pragma unroll
    for (int i = 0; i < 8; i++) {
        int row = rowBase + ty * 8 + i;
        #pragma unroll
        for (int j = 0; j < 8; j++) {
            int col = colBase + tx * 8 + j;
            float pre = __fadd_rn(acc[i][j], bias[col]);
            float t = xla_tanh(pre);
            size_t off = (size_t)row * DC + col;
            g_h[off] = t;
            g_res[off] = t;
        }
    }
}

// ---------------------------------------------------------------------------
// top-2 helpers ((value, index) lexicographic; lower index wins on tie)
// ---------------------------------------------------------------------------
__device__ __forceinline__ bool t2_better(float av, int ai, float bv, int bi) {
    return (av < bv) || (av == bv && ai < bi);
}
__device__ __forceinline__ void t2_merge(float& v1, int& i1, float& v2, int& i2,
                                         float cv1, int ci1, float cv2, int ci2) {
    if (t2_better(cv1, ci1, v1, i1)) {
        if (t2_better(v1, i1, cv2, ci2)) { v2 = v1; i2 = i1; }
        else                             { v2 = cv2; i2 = ci2; }
        v1 = cv1; i1 = ci1;
    } else {
        if (t2_better(cv1, ci1, v2, i2)) { v2 = cv1; i2 = ci1; }
    }
}

// ---------------------------------------------------------------------------
// One RVQ step, tensor-core candidate selection + exact fp32 decision.
//   approx score = e2 - 2*(res.e) via mma.sync tf32 (error <= ~0.16 abs)
//   per-row top-2 approx -> recompute both with the bit-exact serial fp32
//   chain + (r2-2re)+e2 form -> lexicographic pick (== full exact argmin).
// 256 threads = 8 warps: warpM=warp&3 (32 rows), warpN=warp>>2 (64 bins).
// smem [k][m] pitch 129 (conflict-free staging).
// ---------------------------------------------------------------------------
__global__ __launch_bounds__(256, 2)
void rvq_step_kernel(const float* __restrict__ cb_all, int step,
                     float* __restrict__ idx_out) {
    const float* cb = cb_all + (size_t)step * BINS * DC;
    const float* e2g = g_e2 + step * BINS;

    __shared__ unsigned As[32 * 129];
    __shared__ unsigned Bs[32 * 129];
    __shared__ float e2s[128];
    __shared__ float r2row[128];
    __shared__ float c1v[128][2]; __shared__ int c1i[128][2];
    __shared__ float c2v[128][2]; __shared__ int c2i[128][2];
    __shared__ float b1v[128]; __shared__ int b1i[128];
    __shared__ float b2v[128]; __shared__ int b2i[128];
    __shared__ int   bestI[128];
    __shared__ double rs[256];

    int tid = threadIdx.x;
    int warp = tid >> 5, lane = tid & 31;
    int gid = lane >> 2, tg = lane & 3;
    int warpM = warp & 3, warpN = warp >> 2;
    int rowBase = blockIdx.x * 128;

    // r2 per row (XLA row-reduce pattern), 8 warps x 16 rows — exact path
    for (int r = warp * 16; r < warp * 16 + 16; r++) {
        float s = warp_rowsum_sq(g_res + (size_t)(rowBase + r) * DC, lane);
        if (lane == 0) r2row[r] = s;
    }
    if (tid < 128) {
        b1v[tid] = 3.4e38f; b1i[tid] = 0x7fffffff;
        b2v[tid] = 3.4e38f; b2i[tid] = 0x7fffffff;
    }
    __syncthreads();

    for (int bc = 0; bc < BINS; bc += 128) {
        if (tid < 128) e2s[tid] = e2g[bc + tid];

        float acc[2][8][4];
        #pragma unroll
        for (int mt = 0; mt < 2; mt++)
            #pragma unroll
            for (int nt = 0; nt < 8; nt++)
                #pragma unroll
                for (int c = 0; c < 4; c++) acc[mt][nt][c] = 0.f;

        for (int kc = 0; kc < DC; kc += 32) {
            // stage 128x32 A (res) and B (codebook) tiles, tf32, [k][m] pitch 129
            #pragma unroll
            for (int l = 0; l < 4; l++) {
                int fid = tid + l * 256;            // 0..1023
                int m = fid >> 3, kq = (fid & 7) * 4;
                float4 v = *(const float4*)(g_res + (size_t)(rowBase + m) * DC + kc + kq);
                As[(kq + 0) * 129 + m] = f2tf(v.x);
                As[(kq + 1) * 129 + m] = f2tf(v.y);
                As[(kq + 2) * 129 + m] = f2tf(v.z);
                As[(kq + 3) * 129 + m] = f2tf(v.w);
                float4 b = *(const float4*)(cb + (size_t)(bc + m) * DC + kc + kq);
                Bs[(kq + 0) * 129 + m] = f2tf(b.x);
                Bs[(kq + 1) * 129 + m] = f2tf(b.y);
                Bs[(kq + 2) * 129 + m] = f2tf(b.z);
                Bs[(kq + 3) * 129 + m] = f2tf(b.w);
            }
            __syncthreads();
            #pragma unroll
            for (int ks = 0; ks < 4; ks++) {
                int k0 = ks * 8;
                unsigned bfr[8][2];
                #pragma unroll
                for (int nt = 0; nt < 8; nt++) {
                    int n = warpN * 64 + nt * 8 + gid;
                    bfr[nt][0] = Bs[(k0 + tg) * 129 + n];
                    bfr[nt][1] = Bs[(k0 + tg + 4) * 129 + n];
                }
                #pragma unroll
                for (int mt = 0; mt < 2; mt++) {
                    int m = warpM * 32 + mt * 16 + gid;
                    unsigned a0 = As[(k0 + tg) * 129 + m];
                    unsigned a1 = As[(k0 + tg) * 129 + m + 8];
                    unsigned a2 = As[(k0 + tg + 4) * 129 + m];
                    unsigned a3 = As[(k0 + tg + 4) * 129 + m + 8];
                    #pragma unroll
                    for (int nt = 0; nt < 8; nt++)
                        mma_tf32(acc[mt][nt], a0, a1, a2, a3, bfr[nt][0], bfr[nt][1]);
                }
            }
            __syncthreads();
        }

        // approx scoring + per-row top-2 (C frag: c0/c1 row=gid, c2/c3 row=gid+8;
        // cols 2*tg, 2*tg+1 within each 8-col ntile)
        #pragma unroll
        for (int mt = 0; mt < 2; mt++)
        #pragma unroll
        for (int half = 0; half < 2; half++) {
            float v1 = 3.4e38f, v2 = 3.4e38f; int i1 = 0x7fffffff, i2 = 0x7fffffff;
            #pragma unroll
            for (int nt = 0; nt < 8; nt++) {
                int colL = warpN * 64 + nt * 8 + 2 * tg;
                float s0 = fmaf(-2.f, acc[mt][nt][half * 2 + 0], e2s[colL]);
                t2_merge(v1, i1, v2, i2, s0, bc + colL, 3.4e38f, 0x7fffffff);
                float s1 = fmaf(-2.f, acc[mt][nt][half * 2 + 1], e2s[colL + 1]);
                t2_merge(v1, i1, v2, i2, s1, bc + colL + 1, 3.4e38f, 0x7fffffff);
            }
            #pragma unroll
            for (int msk = 1; msk <= 2; msk <<= 1) {
                float ov1 = __shfl_xor_sync(0xffffffffu, v1, msk);
                int   oi1 = __shfl_xor_sync(0xffffffffu, i1, msk);
                float ov2 = __shfl_xor_sync(0xffffffffu, v2, msk);
                int   oi2 = __shfl_xor_sync(0xffffffffu, i2, msk);
                t2_merge(v1, i1, v2, i2, ov1, oi1, ov2, oi2);
            }
            if (tg == 0) {
                int r = warpM * 32 + mt * 16 + half * 8 + gid;
                c1v[r][warpN] = v1; c1i[r][warpN] = i1;
                c2v[r][warpN] = v2; c2i[r][warpN] = i2;
            }
        }
        __syncthreads();
        if (tid < 128) {
            float v1 = b1v[tid], v2 = b2v[tid]; int i1 = b1i[tid], i2 = b2i[tid];
            t2_merge(v1, i1, v2, i2, c1v[tid][0], c1i[tid][0], c2v[tid][0], c2i[tid][0]);
            t2_merge(v1, i1, v2, i2, c1v[tid][1], c1i[tid][1], c2v[tid][1], c2i[tid][1]);
            b1v[tid] = v1; b1i[tid] = i1; b2v[tid] = v2; b2i[tid] = i2;
        }
        __syncthreads();
    }

    // exact decision between the two candidates (bit-identical to full scan)
    if (tid < 128) {
        int i1 = b1i[tid], i2 = b2i[tid];
        const float4* rr = (const float4*)(g_res + (size_t)(rowBase + tid) * DC);
        const float4* p1 = (const float4*)(cb + (size_t)i1 * DC);
        const float4* p2 = (const float4*)(cb + (size_t)i2 * DC);
        float re1 = 0.f, re2 = 0.f;
        for (int k4 = 0; k4 < DC / 4; k4++) {
            float4 r4 = rr[k4]; float4 a4 = p1[k4]; float4 b4 = p2[k4];
            re1 = fmaf(r4.x, a4.x, re1); re1 = fmaf(r4.y, a4.y, re1);
            re1 = fmaf(r4.z, a4.z, re1); re1 = fmaf(r4.w, a4.w, re1);
            re2 = fmaf(r4.x, b4.x, re2); re2 = fmaf(r4.y, b4.y, re2);
            re2 = fmaf(r4.z, b4.z, re2); re2 = fmaf(r4.w, b4.w, re2);
        }
        float r2 = r2row[tid];
        float d1 = __fadd_rn(__fsub_rn(r2, __fmul_rn(2.0f, re1)), e2g[i1]);
        float d2 = __fadd_rn(__fsub_rn(r2, __fmul_rn(2.0f, re2)), e2g[i2]);
        int chosen = i1;
        if (d2 < d1 || (d2 == d1 && i2 < i1)) chosen = i2;
        bestI[tid] = chosen;
        idx_out[(size_t)step * MTOT + rowBase + tid] = (float)chosen;
    }
    __syncthreads();

    // gather + residual update + q accumulation + commit partial
    double csum = 0.0;
    for (int r = 0; r < 128; r++) {
        int gi = bestI[r];
        float c = cb[(size_t)gi * DC + tid];
        size_t off = (size_t)(rowBase + r) * DC + tid;
        float old = g_res[off];
        float t = __fsub_rn(c, old);
        csum += (double)__fmul_rn(t, t);
        g_res[off] = __fsub_rn(old, c);
        g_q[off] = (step == 0) ? c : __fadd_rn(g_q[off], c);
    }
    rs[tid] = csum;
    __syncthreads();
    #pragma unroll
    for (int s = 128; s; s >>= 1) {
        if (tid < s) rs[tid] += rs[tid + s];
        __syncthreads();
    }
    if (tid == 0) g_partial[step * RVQ_BLOCKS + blockIdx.x] = rs[0];
}

__global__ void finalize_kernel(float* __restrict__ commit_out) {
    if (blockIdx.x == 0 && threadIdx.x == 0) {
        double total = 0.0;
        for (int n = 0; n < NQ; n++) {
            double s = 0.0;
            for (int b = 0; b < RVQ_BLOCKS; b++) s += g_partial[n * RVQ_BLOCKS + b];
            total += s / ((double)MTOT * (double)DC);
        }
        *commit_out = (float)(0.1 * total);
    }
}

// ---------------------------------------------------------------------------
// proj_out: out = (h + (sumq - h)) @ out_w^T + out_b. 128x128x16, 8x8 scalar.
// ---------------------------------------------------------------------------
__global__ __launch_bounds__(256, 2)
void proj_out_kernel(const float* __restrict__ Bw,
                     const float* __restrict__ bias,
                     float* __restrict__ C) {
    __shared__ float As[16][128];
    __shared__ float Bs[16][128];

    int tid = threadIdx.x;
    int tx = tid & 15, ty = tid >> 4;
    int rowBase = blockIdx.x * 128;
    int colBase = blockIdx.y * 128;

    float acc[8][8];
    #pragma unroll
    for (int i = 0; i < 8; i++)
        #pragma unroll
        for (int j = 0; j < 8; j++) acc[i][j] = 0.f;

    for (int kc = 0; kc < DC; kc += 16) {
        #pragma unroll
        for (int l = 0; l < 2; l++) {
            int id = tid + l * 256;
            int r = id >> 2, kq = (id & 3) * 4;
            size_t off = (size_t)(rowBase + r) * DC + kc + kq;
            float4 h4 = *(const float4*)(g_h + off);
            float4 q4 = *(const float4*)(g_q + off);
            As[kq + 0][r] = __fadd_rn(h4.x, __fsub_rn(q4.x, h4.x));
            As[kq + 1][r] = __fadd_rn(h4.y, __fsub_rn(q4.y, h4.y));
            As[kq + 2][r] = __fadd_rn(h4.z, __fsub_rn(q4.z, h4.z));
            As[kq + 3][r] = __fadd_rn(h4.w, __fsub_rn(q4.w, h4.w));
            float4 b = *(const float4*)(Bw + (size_t)(colBase + r) * DC + kc + kq);
            Bs[kq + 0][r] = b.x; Bs[kq + 1][r] = b.y;
            Bs[kq + 2][r] = b.z; Bs[kq + 3][r] = b.w;
        }
        __syncthreads();
        #pragma unroll
        for (int kk = 0; kk < 16; kk++) {
            float a[8], b[8];
            #pragma unroll
            for (int i = 0; i < 8; i++) a[i] = As[kk][ty * 8 + i];
            #pragma unroll
            for (int j = 0; j < 8; j++) b[j] = Bs[kk][tx * 8 + j];
            #pragma unroll
            for (int i = 0; i < 8; i++)
                #pragma unroll
                for (int j = 0; j < 8; j++) acc[i][j] = fmaf(a[i], b[j], acc[i][j]);
        }
        __syncthreads();
    }

    #pragma unroll
    for (int i = 0; i < 8; i++) {
        int row = rowBase + ty * 8 + i;
        #pragma unroll
        for (int j = 0; j < 8; j++) {
            int col = colBase + tx * 8 + j;
            C[(size_t)row * DIN + col] = __fadd_rn(acc[i][j], bias[col]);
        }
    }
}

// ---------------------------------------------------------------------------
extern "C" void kernel_launch(void* const* d_in, const int* in_sizes, int n_in,
                              void* d_out, int out_size) {
    const float* x     = (const float*)d_in[0];   // [8,4096,512]
    const float* in_w  = (const float*)d_in[1];   // [256,512]
    const float* in_b  = (const float*)d_in[2];   // [256]
    const float* out_w = (const float*)d_in[3];   // [512,256]
    const float* out_b = (const float*)d_in[4];   // [512]
    const float* cb    = (const float*)d_in[5];   // [8,1024,256]

    float* out_f = (float*)d_out;

    float* idx_f    = nullptr;
    float* commit_f = nullptr;
    if ((size_t)out_size >= OUT_ELEMS + IDX_ELEMS + 1) {
        idx_f    = out_f + OUT_ELEMS;
        commit_f = out_f + OUT_ELEMS + IDX_ELEMS;
    } else if ((size_t)out_size >= OUT_ELEMS + IDX_ELEMS) {
        idx_f = out_f + OUT_ELEMS;
    }
    if (!idx_f)    cudaGetSymbolAddress((void**)&idx_f,    g_idx_sink);
    if (!commit_f) cudaGetSymbolAddress((void**)&commit_f, g_commit_sink);

    e2_kernel<<<64, 256>>>(cb);

    {
        dim3 grid(MTOT / 128, DC / 128);
        proj_in_kernel<<<grid, 256>>>(x, in_w, in_b);
    }

    for (int n = 0; n < NQ; n++)
        rvq_step_kernel<<<RVQ_BLOCKS, 256>>>(cb, n, idx_f);

    finalize_kernel<<<1, 32>>>(commit_f);

    {
        dim3 grid(MTOT / 128, DIN / 128);
        proj_out_kernel<<<grid, 256>>>(out_w, out_b, out_f);
    }
}